// round 1
// baseline (speedup 1.0000x reference)
#include <cuda_runtime.h>
#include <math.h>

#define NL 8
#define NE 8
#define ND 256
#define NB 16384
#define NH1 64
#define NH2 32

#define TM 32
#define NTH 256

// ---- shared memory layout (float offsets) ----
// xsT   [256][36]  : x tile transposed (d-major, padded)       9216
// big   region     : Ws[32][132] / W2s[64][68] | h1sT[128][36] ; W3s[32][260] overlays all
// h2sT  [64][36]   : scaled h2 transposed                      2304
// wsoft [32][8]    : softmax weights
// b1s[128] b2s[64] b3s[256]
#define OFF_XST   0
#define OFF_BIG   9216
#define OFF_H1    (OFF_BIG + 4352)            // h1sT after Ws/W2s region
#define OFF_H2S   (OFF_BIG + 8960)
#define OFF_WSOFT (OFF_H2S + 2304)
#define OFF_B1    (OFF_WSOFT + 256)
#define OFF_B2    (OFF_B1 + 128)
#define OFF_B3    (OFF_B2 + 64)
#define SMEM_FLOATS (OFF_B3 + 256)            // 21184 floats
#define SMEM_BYTES  (SMEM_FLOATS * 4)         // 84736 bytes

__global__ void __launch_bounds__(NTH, 2)
moe_fused_kernel(const float* __restrict__ src,
                 const float* __restrict__ W1, const float* __restrict__ b1,
                 const float* __restrict__ W2, const float* __restrict__ b2,
                 const float* __restrict__ W3, const float* __restrict__ b3,
                 const float* __restrict__ masks,
                 float* __restrict__ out)
{
    extern __shared__ float sm[];
    float* xsT   = sm + OFF_XST;   // [d][36] rows r in 0..31
    float* Ws    = sm + OFF_BIG;   // [k][132]
    float* W2s   = sm + OFF_BIG;   // [h][68]
    float* h1sT  = sm + OFF_H1;    // [h'][36]
    float* W3s   = sm + OFF_BIG;   // [k][260]
    float* h2sT  = sm + OFF_H2S;   // [j'][36]
    float* wsoft = sm + OFF_WSOFT; // [r][8]
    float* b1s   = sm + OFF_B1;
    float* b2s   = sm + OFF_B2;
    float* b3s   = sm + OFF_B3;

    const int tid = threadIdx.x;
    const int rowbase = blockIdx.x * TM;
    const int rg = tid >> 5;   // row group: rows 4*rg .. 4*rg+3
    const int cg = tid & 31;   // col group

    // ---- load x tile, transposed into xsT (conflict-free float2 pattern) ----
    {
        const int r = (tid >> 2) & 31;
        const float* srcp = src + (size_t)(rowbase + r) * ND;
        #pragma unroll
        for (int m = 0; m < 16; m++) {
            int idx = tid + 256 * m;
            int d2 = (idx & 3) + 4 * (idx >> 7);   // 0..127
            float2 v = *(const float2*)(srcp + 2 * d2);
            xsT[(2 * d2 + 0) * 36 + r] = v.x;
            xsT[(2 * d2 + 1) * 36 + r] = v.y;
        }
    }
    __syncthreads();

    float xacc[4][8];   // persistent next-x accumulators: rows 4rg+i, cols 8cg+j

    for (int l = 0; l < NL; l++) {
        // ---- softmax weights for this layer ----
        if (tid < TM) {
            const float* mrow = masks + ((size_t)l * NB + rowbase + tid) * NE;
            float m0[8]; float mx = -1e30f;
            #pragma unroll
            for (int e = 0; e < 8; e++) { m0[e] = mrow[e]; mx = fmaxf(mx, m0[e]); }
            float s = 0.f;
            #pragma unroll
            for (int e = 0; e < 8; e++) { m0[e] = expf(m0[e] - mx); s += m0[e]; }
            s = 1.f / s;
            #pragma unroll
            for (int e = 0; e < 8; e++) wsoft[tid * 8 + e] = m0[e] * s;
        }
        #pragma unroll
        for (int i = 0; i < 4; i++)
            #pragma unroll
            for (int j = 0; j < 8; j++) xacc[i][j] = 0.f;

        for (int ep = 0; ep < 4; ep++) {        // expert pairs
            const int e0 = ep * 2;
            const float* W1p = W1 + (size_t)(l * NE + e0) * NH1 * ND;  // [128][256]

            // ================= Phase A: GEMM1 (pair) h1 = relu(x*W1^T + b1) =================
            float hacc[4][4];
            #pragma unroll
            for (int i = 0; i < 4; i++)
                #pragma unroll
                for (int j = 0; j < 4; j++) hacc[i][j] = 0.f;

            float2 wreg[8];
            // prefetch k-chunk 0
            #pragma unroll
            for (int m = 0; m < 8; m++) {
                int idx = tid + 256 * m;
                int h  = (idx >> 2) & 127;
                int k2 = (idx & 3) + 4 * (idx >> 9);
                wreg[m] = *(const float2*)(W1p + h * ND + 2 * k2);
            }
            for (int kc = 0; kc < 8; kc++) {
                __syncthreads();   // Ws region free
                #pragma unroll
                for (int m = 0; m < 8; m++) {
                    int idx = tid + 256 * m;
                    int h  = (idx >> 2) & 127;
                    int k2 = (idx & 3) + 4 * (idx >> 9);
                    Ws[(2 * k2 + 0) * 132 + h] = wreg[m].x;
                    Ws[(2 * k2 + 1) * 132 + h] = wreg[m].y;
                }
                if (kc == 0 && tid < 128) b1s[tid] = b1[(size_t)(l * NE + e0) * NH1 + tid];
                __syncthreads();
                if (kc < 7) {   // prefetch next chunk (latency hidden behind compute)
                    #pragma unroll
                    for (int m = 0; m < 8; m++) {
                        int idx = tid + 256 * m;
                        int h  = (idx >> 2) & 127;
                        int k2 = (idx & 3) + 4 * (idx >> 9);
                        wreg[m] = *(const float2*)(W1p + h * ND + (kc + 1) * 32 + 2 * k2);
                    }
                }
                const float* xp = xsT + (kc * 32) * 36 + 4 * rg;
                const float* wp = Ws + 4 * cg;
                #pragma unroll
                for (int k = 0; k < 32; k++) {
                    float4 xt = *(const float4*)(xp + k * 36);
                    float4 wt = *(const float4*)(wp + k * 132);
                    float xr[4] = {xt.x, xt.y, xt.z, xt.w};
                    float wr[4] = {wt.x, wt.y, wt.z, wt.w};
                    #pragma unroll
                    for (int i = 0; i < 4; i++)
                        #pragma unroll
                        for (int j = 0; j < 4; j++)
                            hacc[i][j] += xr[i] * wr[j];
                }
            }
            // epilogue: bias + relu -> h1sT (transposed)
            #pragma unroll
            for (int j = 0; j < 4; j++) {
                int h = 4 * cg + j;
                float bb = b1s[h];
                #pragma unroll
                for (int i = 0; i < 4; i++) {
                    float v = fmaxf(hacc[i][j] + bb, 0.f);
                    h1sT[h * 36 + 4 * rg + i] = v;
                }
            }
            __syncthreads();

            // ================= Phase B: GEMM2 (pair, block-diagonal) =================
            {
                const float* W2p = W2 + (size_t)(l * NE + e0) * NH2 * NH1;
                #pragma unroll
                for (int m = 0; m < 8; m++) {
                    int idx = tid + 256 * m;
                    int jp = (idx >> 2) & 63;
                    int h2 = (idx & 3) + 4 * ((idx >> 8) & 7);
                    float2 v = *(const float2*)(W2p + jp * NH1 + 2 * h2);
                    W2s[(2 * h2 + 0) * 68 + jp] = v.x;
                    W2s[(2 * h2 + 1) * 68 + jp] = v.y;
                }
                if (tid < 64) b2s[tid] = b2[(size_t)(l * NE + e0) * NH2 + tid];
            }
            __syncthreads();
            {
                const int el2 = cg >> 4;   // which expert of the pair this thread's cols belong to
                float h2acc[4][2];
                #pragma unroll
                for (int i = 0; i < 4; i++) { h2acc[i][0] = 0.f; h2acc[i][1] = 0.f; }
                const float* h1b = h1sT + el2 * 64 * 36 + 4 * rg;
                const float* w2b = W2s + 2 * cg;
                #pragma unroll
                for (int h = 0; h < 64; h++) {
                    float4 ht = *(const float4*)(h1b + h * 36);
                    float2 wt = *(const float2*)(w2b + h * 68);
                    float hr[4] = {ht.x, ht.y, ht.z, ht.w};
                    #pragma unroll
                    for (int i = 0; i < 4; i++) {
                        h2acc[i][0] += hr[i] * wt.x;
                        h2acc[i][1] += hr[i] * wt.y;
                    }
                }
                // epilogue: bias, relu, pre-scale by softmax weight, store transposed
                #pragma unroll
                for (int jj = 0; jj < 2; jj++) {
                    int jp = 2 * cg + jj;
                    float bb = b2s[jp];
                    #pragma unroll
                    for (int i = 0; i < 4; i++) {
                        int r = 4 * rg + i;
                        float wgt = wsoft[r * 8 + e0 + el2];
                        h2sT[jp * 36 + r] = fmaxf(h2acc[i][jj] + bb, 0.f) * wgt;
                    }
                }
            }
            __syncthreads();

            // ================= Phase C: GEMM3 per expert, accumulate into xacc =================
            for (int el = 0; el < 2; el++) {
                const float* W3p = W3 + (size_t)(l * NE + e0 + el) * ND * NH2;  // [256][32]
                #pragma unroll
                for (int m = 0; m < 16; m++) {
                    int idx = tid + 256 * m;
                    int d  = (idx >> 2) & 255;
                    int k2 = (idx & 3) + 4 * (idx >> 10);
                    float2 v = *(const float2*)(W3p + d * NH2 + 2 * k2);
                    W3s[(2 * k2 + 0) * 260 + d] = v.x;
                    W3s[(2 * k2 + 1) * 260 + d] = v.y;
                }
                b3s[tid] = b3[(size_t)(l * NE + e0 + el) * ND + tid];
                __syncthreads();
                {
                    const float* h2b = h2sT + el * 32 * 36 + 4 * rg;
                    const float* w3b = W3s + 8 * cg;
                    #pragma unroll
                    for (int k = 0; k < 32; k++) {
                        float4 ht = *(const float4*)(h2b + k * 36);
                        float4 w0 = *(const float4*)(w3b + k * 260);
                        float4 w1 = *(const float4*)(w3b + k * 260 + 4);
                        float hr[4] = {ht.x, ht.y, ht.z, ht.w};
                        float wr[8] = {w0.x, w0.y, w0.z, w0.w, w1.x, w1.y, w1.z, w1.w};
                        #pragma unroll
                        for (int i = 0; i < 4; i++)
                            #pragma unroll
                            for (int j = 0; j < 8; j++)
                                xacc[i][j] += hr[i] * wr[j];
                    }
                    // weighted b3 contribution: sum_e w[r,e] * b3[e,c]
                    #pragma unroll
                    for (int i = 0; i < 4; i++) {
                        float wgt = wsoft[(4 * rg + i) * 8 + e0 + el];
                        #pragma unroll
                        for (int j = 0; j < 8; j++)
                            xacc[i][j] += wgt * b3s[8 * cg + j];
                    }
                }
                __syncthreads();
            }
        } // expert pairs

        // ---- layer output: either to global (last layer) or back into xsT ----
        if (l == NL - 1) {
            #pragma unroll
            for (int i = 0; i < 4; i++) {
                float* op = out + (size_t)(rowbase + 4 * rg + i) * ND + 8 * cg;
                float4 a = make_float4(xacc[i][0], xacc[i][1], xacc[i][2], xacc[i][3]);
                float4 b = make_float4(xacc[i][4], xacc[i][5], xacc[i][6], xacc[i][7]);
                *(float4*)op = a;
                *(float4*)(op + 4) = b;
            }
        } else {
            #pragma unroll
            for (int i = 0; i < 4; i++) {
                int r = 4 * rg + i;
                #pragma unroll
                for (int jj = 0; jj < 8; jj++) {
                    int j = (jj + cg) & 7;   // stagger to reduce bank conflicts
                    xsT[(8 * cg + j) * 36 + r] = xacc[i][j];
                }
            }
            __syncthreads();
        }
    } // layers
}

extern "C" void kernel_launch(void* const* d_in, const int* in_sizes, int n_in,
                              void* d_out, int out_size)
{
    const float* src   = (const float*)d_in[0];
    const float* W1    = (const float*)d_in[1];
    const float* b1    = (const float*)d_in[2];
    const float* W2    = (const float*)d_in[3];
    const float* b2    = (const float*)d_in[4];
    const float* W3    = (const float*)d_in[5];
    const float* b3    = (const float*)d_in[6];
    const float* masks = (const float*)d_in[7];
    float* out = (float*)d_out;

    (void)in_sizes; (void)n_in; (void)out_size;

    cudaFuncSetAttribute(moe_fused_kernel,
                         cudaFuncAttributeMaxDynamicSharedMemorySize, SMEM_BYTES);
    moe_fused_kernel<<<NB / TM, NTH, SMEM_BYTES>>>(src, W1, b1, W2, b2, W3, b3, masks, out);
}